// round 5
// baseline (speedup 1.0000x reference)
#include <cuda_runtime.h>
#include <cuda_bf16.h>
#include <math.h>

// ---------------------------------------------------------------------------
// RITS / BRITS-style recurrent imputation. B=512, T=128, D=H=128.
// Launches: prep(+denom), mergedGEMM(Gh,Gx,Gm), betaGEMM, seq  (4 total)
// ---------------------------------------------------------------------------

#define T_STEPS  128
#define DD       128
#define N_STASH  9            // k4 slices of WgQ held in SMEM (9*8KB = 72KB)

typedef unsigned long long ull;

__device__ __align__(16) float g_Gh[8388608];     // [BT, 128]
__device__ __align__(16) float g_Gx[8388608];     // [BT, 128]
__device__ __align__(16) float g_Beta[8388608];   // [BT, 128]
__device__ __align__(16) float g_Gm[33554432];    // [BT, 512]
__device__ __align__(16) float g_den[128];
__device__ __align__(16) float g_WthT[16384];
__device__ __align__(16) float g_WtxT[16384];
__device__ __align__(16) float g_WhrQ[16384];     // [32 k4][128 j][4 e]
__device__ __align__(16) float g_WfrQ[16384];     // [32 k4][128 j][4 e]
__device__ __align__(16) float g_WgQ[131072];     // [64 k4][512 n][4 e]

__device__ __forceinline__ float sigmoidf_(float x) { return 1.0f / (1.0f + expf(-x)); }

__device__ __forceinline__ void ffma2(ull& d, ull a, ull b) {
    asm("fma.rn.f32x2 %0, %1, %2, %0;" : "+l"(d) : "l"(a), "l"(b));
}
__device__ __forceinline__ ull packf2(float a, float b) {
    ull u; asm("mov.b64 %0, {%1, %2};" : "=l"(u) : "f"(a), "f"(b)); return u;
}
__device__ __forceinline__ float hsum2(ull u) {
    float x, y; asm("mov.b64 {%0, %1}, %2;" : "=f"(x), "=f"(y) : "l"(u));
    return x + y;
}
__device__ __forceinline__ float2 unpackf2(ull u) {
    float2 r; asm("mov.b64 {%0, %1}, %2;" : "=f"(r.x), "=f"(r.y) : "l"(u));
    return r;
}

// ---------------------------------------------------------------------------
// Prep: transposes + quad-k repacks + denom (blocks < 128)
// ---------------------------------------------------------------------------
__global__ void prep_weights(const float* __restrict__ Wth, const float* __restrict__ Wtx,
                             const float* __restrict__ Whr, const float* __restrict__ Wfr,
                             const float* __restrict__ Wk,  const float* __restrict__ Wr,
                             const float* __restrict__ masks,
                             float* __restrict__ WthT, float* __restrict__ WtxT,
                             float* __restrict__ WhrQ, float* __restrict__ WfrQ,
                             float* __restrict__ WgQ,  float* __restrict__ den)
{
    int idx = blockIdx.x * blockDim.x + threadIdx.x;
    if (idx < 16384) {
        int k = idx >> 7, j = idx & 127;
        WthT[idx] = Wth[j * 128 + k];
        WtxT[idx] = Wtx[j * 128 + k];
        int k4 = idx >> 9, rem = idx & 511, jj = rem >> 2, e = rem & 3;
        int kk = 4 * k4 + e;
        WhrQ[idx] = Whr[kk * 128 + jj];
        WfrQ[idx] = Wfr[jj * 128 + kk];
    }
    if (idx < 131072) {
        int k4 = idx >> 11, rem = idx & 2047, n = rem >> 2, e = rem & 3;
        int k = 4 * k4 + e;
        WgQ[idx] = (k < 128) ? Wk[k * 512 + n] : Wr[(k - 128) * 512 + n];
    }
    if (blockIdx.x < 128) {
        int t = blockIdx.x;
        float s = 0.0f;
        for (int i = threadIdx.x; i < 512 * 128; i += blockDim.x) {
            int b = i >> 7, d = i & 127;
            s += masks[((size_t)b * T_STEPS + t) * DD + d];
        }
        __shared__ float red[256];
        red[threadIdx.x] = s;
        __syncthreads();
        for (int off = 128; off > 0; off >>= 1) {
            if (threadIdx.x < off) red[threadIdx.x] += red[threadIdx.x + off];
            __syncthreads();
        }
        if (threadIdx.x == 0) den[t] = red[0] + 1e-6f;
    }
}

// ---------------------------------------------------------------------------
// GEMM body: C[bm:bm+64, bn:bn+64] = epi(A @ B + bias), packed f32x2 FMAs.
// A split column-wise at k=128 (A1/A2, both lda=128). BK=16, 256 threads.
// ---------------------------------------------------------------------------
__device__ __forceinline__ void gemm_body(
    const float* __restrict__ A1, const float* __restrict__ A2,
    const float* __restrict__ B, const float* __restrict__ bias,
    float* __restrict__ C, int N, int K, int epi, int bm, int bn)
{
    __shared__ float As[64][16];
    __shared__ float Bs[16][64];

    const int tid = threadIdx.x;
    const int tx = tid & 15;
    const int ty = tid >> 4;
    const int arow = tid >> 2;
    const int ak4 = (tid & 3) * 4;
    const int bk = tid >> 4;
    const int bn4 = (tid & 15) * 4;

    ull acc[4][2];
#pragma unroll
    for (int i = 0; i < 4; i++) { acc[i][0] = 0ULL; acc[i][1] = 0ULL; }

    for (int k0 = 0; k0 < K; k0 += 16) {
        const float* Ab;
        int kloc;
        if (k0 < 128) { Ab = A1; kloc = k0; } else { Ab = A2; kloc = k0 - 128; }
        float4 av = *(const float4*)&Ab[(size_t)(bm + arow) * 128 + kloc + ak4];
        *(float4*)&As[arow][ak4] = av;
        float4 bv = *(const float4*)&B[(size_t)(k0 + bk) * N + bn + bn4];
        *(float4*)&Bs[bk][bn4] = bv;
        __syncthreads();
#pragma unroll
        for (int kk = 0; kk < 16; kk++) {
            ull b01 = *(const ull*)&Bs[kk][tx * 4];
            ull b23 = *(const ull*)&Bs[kk][tx * 4 + 2];
#pragma unroll
            for (int i = 0; i < 4; i++) {
                float a = As[ty * 4 + i][kk];
                ull ap = packf2(a, a);
                ffma2(acc[i][0], ap, b01);
                ffma2(acc[i][1], ap, b23);
            }
        }
        __syncthreads();
    }

#pragma unroll
    for (int i = 0; i < 4; i++) {
        float2 c01 = unpackf2(acc[i][0]);
        float2 c23 = unpackf2(acc[i][1]);
        float4 ov;
        ov.x = c01.x + bias[bn + tx * 4 + 0];
        ov.y = c01.y + bias[bn + tx * 4 + 1];
        ov.z = c23.x + bias[bn + tx * 4 + 2];
        ov.w = c23.y + bias[bn + tx * 4 + 3];
        if (epi == 0) {
            ov.x = expf(-fmaxf(ov.x, 0.0f));
            ov.y = expf(-fmaxf(ov.y, 0.0f));
            ov.z = expf(-fmaxf(ov.z, 0.0f));
            ov.w = expf(-fmaxf(ov.w, 0.0f));
        }
        *(float4*)&C[(size_t)(bm + ty * 4 + i) * N + bn + tx * 4] = ov;
    }
}

// Merged GEMM: y 0-1 -> Gh, y 2-3 -> Gx, y 4-11 -> Gm
__global__ void __launch_bounds__(256) gemm_merged(
    const float* __restrict__ deltas, const float* __restrict__ masks,
    const float* __restrict__ WthT, const float* __restrict__ bth,
    const float* __restrict__ WtxT, const float* __restrict__ btx,
    const float* __restrict__ WkBot, const float* __restrict__ bl,
    float* __restrict__ Gh, float* __restrict__ Gx, float* __restrict__ Gm)
{
    int bm = blockIdx.x * 64;
    int y = blockIdx.y;
    if (y < 2)       gemm_body(deltas, nullptr, WthT, bth, Gh, 128, 128, 0, bm, y * 64);
    else if (y < 4)  gemm_body(deltas, nullptr, WtxT, btx, Gx, 128, 128, 0, bm, (y - 2) * 64);
    else             gemm_body(masks,  nullptr, WkBot, bl, Gm, 512, 128, 1, bm, (y - 4) * 64);
}

// Beta GEMM (depends on Gx)
__global__ void __launch_bounds__(256) gemm_beta(
    const float* __restrict__ Gx, const float* __restrict__ masks,
    const float* __restrict__ Wwc, const float* __restrict__ bwc,
    float* __restrict__ Beta)
{
    gemm_body(Gx, masks, Wwc, bwc, Beta, 128, 256, 1, blockIdx.x * 64, blockIdx.y * 64);
}

// ---------------------------------------------------------------------------
// Sequential recurrence: 128 CTAs x 4 rows x 512 threads.
// Phase E split: h-half (k4 32..63) right after S1 overlaps B/C;
// cc-half (k4 0..8 from SMEM stash, 9..31 from L2) after S3.
// ---------------------------------------------------------------------------
__global__ void __launch_bounds__(512, 1) seq_kernel(
    const float* __restrict__ values, const float* __restrict__ masks,
    const float* __restrict__ WhrQ_g, const float* __restrict__ bhr,
    const float* __restrict__ bfr,    const float* __restrict__ WfrQ_g,
    const float* __restrict__ Gh,     const float* __restrict__ Beta,
    const float* __restrict__ Gm,     const float* __restrict__ den,
    const float* __restrict__ Wd,     const float* __restrict__ bd,
    const float* __restrict__ Wo,     const float* __restrict__ bo,
    const float* __restrict__ WgQ,
    float* __restrict__ out_pred, float* __restrict__ out_imp,
    float* __restrict__ out_loss)
{
    extern __shared__ float sm[];
    float* sWhrQ = sm;                       // 16384
    float* sWfrQ = sm + 16384;               // 16384
    float* sWgC  = sm + 32768;               // 18432 (N_STASH * 2048)
    float* sh    = sm + 51200;               // 512
    float* sc    = sh + 512;                 // 512
    float* sxc   = sc + 512;                 // 512
    float* scc   = sxc + 512;                // 512
    float* sg    = scc + 512;                // 2048
    float* sbhr  = sg + 2048;                // 128
    float* sbfr  = sbhr + 128;               // 128

    const int tid = threadIdx.x;
    const int b0 = blockIdx.x * 4;

    for (int i = tid; i < 16384; i += 512) { sWhrQ[i] = WhrQ_g[i]; sWfrQ[i] = WfrQ_g[i]; }
    for (int i = tid; i < N_STASH * 2048; i += 512) sWgC[i] = WgQ[i];
    if (tid < 128) { sbhr[tid] = bhr[tid]; sbfr[tid] = bfr[tid]; }
    if (tid < 512) { sh[tid] = 0.0f; sc[tid] = 0.0f; }
    __syncthreads();

    const int j = tid & 127;
    const int q = tid >> 7;
    const size_t rowbase = (size_t)(b0 + q) * T_STEPS;

    float lsum = 0.0f;

    float cx = values[rowbase * DD + j];
    float cm = masks[rowbase * DD + j];
    float cg = Gh[rowbase * DD + j];
    float cb = Beta[rowbase * DD + j];
    float cden = den[0];

    const float* wq  = WgQ + (size_t)tid * 4;     // gate col = tid
    const float* wqc = sWgC + (size_t)tid * 4;

    for (int t = 0; t < T_STEPS; t++) {
        const size_t bt = rowbase + t;

        // --- Phase A: decay h ---
        float x = cx, m = cm;
        float h = sh[q * DD + j] * cg;
        sh[q * DD + j] = h;
        float rd = 1.0f / cden;
        float be = cb;
        __syncthreads();                                   // S1

        // --- prefetch next step + Gm(t) ---
        {
            int tn = (t + 1 < T_STEPS) ? (t + 1) : (T_STEPS - 1);
            size_t nb = rowbase + tn;
            cx = values[nb * DD + j];
            cm = masks[nb * DD + j];
            cg = Gh[nb * DD + j];
            cb = Beta[nb * DD + j];
            cden = den[tn];
        }
        ull acc0, acc1, acc2, acc3;
        {
            float g0 = Gm[((size_t)(b0 + 0) * T_STEPS + t) * 512 + tid];
            float g1 = Gm[((size_t)(b0 + 1) * T_STEPS + t) * 512 + tid];
            float g2 = Gm[((size_t)(b0 + 2) * T_STEPS + t) * 512 + tid];
            float g3 = Gm[((size_t)(b0 + 3) * T_STEPS + t) * 512 + tid];
            acc0 = packf2(g0, 0.0f); acc1 = packf2(g1, 0.0f);
            acc2 = packf2(g2, 0.0f); acc3 = packf2(g3, 0.0f);
        }

        // --- Phase E (h-half): gates += h @ Wg[128:256], k4 32..63 streamed ---
#pragma unroll 4
        for (int k4 = 32; k4 < 64; k4++) {
            ulonglong2 w = *(const ulonglong2*)&wq[(size_t)k4 * 2048];
            int ko = (k4 - 32) * 4;
            ulonglong2 v0 = *(const ulonglong2*)&sh[0 * DD + ko];
            ulonglong2 v1 = *(const ulonglong2*)&sh[1 * DD + ko];
            ulonglong2 v2 = *(const ulonglong2*)&sh[2 * DD + ko];
            ulonglong2 v3 = *(const ulonglong2*)&sh[3 * DD + ko];
            ffma2(acc0, v0.x, w.x); ffma2(acc0, v0.y, w.y);
            ffma2(acc1, v1.x, w.x); ffma2(acc1, v1.y, w.y);
            ffma2(acc2, v2.x, w.x); ffma2(acc2, v2.y, w.y);
            ffma2(acc3, v3.x, w.x); ffma2(acc3, v3.y, w.y);
        }

        // --- Phase B: x_hat = h @ Whr + bhr ---
        ull a = packf2(sbhr[j], 0.0f);
#pragma unroll 8
        for (int k4 = 0; k4 < 32; k4++) {
            ulonglong2 w = *(const ulonglong2*)&sWhrQ[k4 * 512 + j * 4];
            ulonglong2 v = *(const ulonglong2*)&sh[q * DD + k4 * 4];
            ffma2(a, v.x, w.x);
            ffma2(a, v.y, w.y);
        }
        float xh = hsum2(a);
        float xc = m * x + (1.0f - m) * xh;
        sxc[q * DD + j] = xc;
        lsum += fabsf(x - xh) * m * rd;
        __syncthreads();                                   // S2

        // --- Phase C: z_hat = x_c @ Wfr^T + bfr ---
        a = packf2(sbfr[j], 0.0f);
#pragma unroll 8
        for (int k4 = 0; k4 < 32; k4++) {
            ulonglong2 w = *(const ulonglong2*)&sWfrQ[k4 * 512 + j * 4];
            ulonglong2 v = *(const ulonglong2*)&sxc[q * DD + k4 * 4];
            ffma2(a, v.x, w.x);
            ffma2(a, v.y, w.y);
        }
        float zh = hsum2(a);
        lsum += fabsf(x - zh) * m * rd;

        // --- Phase D: c_hat / c_c / imputation ---
        float ch = be * zh + (1.0f - be) * xh;
        lsum += fabsf(x - ch) * m * rd;
        float cc = m * x + (1.0f - m) * ch;
        scc[q * DD + j] = cc;
        out_imp[bt * DD + j] = cc;
        __syncthreads();                                   // S3

        // --- Phase E (cc-half): k4 0..8 from SMEM stash, 9..31 from L2 ---
#pragma unroll
        for (int k4 = 0; k4 < N_STASH; k4++) {
            ulonglong2 w = *(const ulonglong2*)&wqc[k4 * 2048];
            int ko = k4 * 4;
            ulonglong2 v0 = *(const ulonglong2*)&scc[0 * DD + ko];
            ulonglong2 v1 = *(const ulonglong2*)&scc[1 * DD + ko];
            ulonglong2 v2 = *(const ulonglong2*)&scc[2 * DD + ko];
            ulonglong2 v3 = *(const ulonglong2*)&scc[3 * DD + ko];
            ffma2(acc0, v0.x, w.x); ffma2(acc0, v0.y, w.y);
            ffma2(acc1, v1.x, w.x); ffma2(acc1, v1.y, w.y);
            ffma2(acc2, v2.x, w.x); ffma2(acc2, v2.y, w.y);
            ffma2(acc3, v3.x, w.x); ffma2(acc3, v3.y, w.y);
        }
#pragma unroll 4
        for (int k4 = N_STASH; k4 < 32; k4++) {
            ulonglong2 w = *(const ulonglong2*)&wq[(size_t)k4 * 2048];
            int ko = k4 * 4;
            ulonglong2 v0 = *(const ulonglong2*)&scc[0 * DD + ko];
            ulonglong2 v1 = *(const ulonglong2*)&scc[1 * DD + ko];
            ulonglong2 v2 = *(const ulonglong2*)&scc[2 * DD + ko];
            ulonglong2 v3 = *(const ulonglong2*)&scc[3 * DD + ko];
            ffma2(acc0, v0.x, w.x); ffma2(acc0, v0.y, w.y);
            ffma2(acc1, v1.x, w.x); ffma2(acc1, v1.y, w.y);
            ffma2(acc2, v2.x, w.x); ffma2(acc2, v2.y, w.y);
            ffma2(acc3, v3.x, w.x); ffma2(acc3, v3.y, w.y);
        }
        sg[0 * 512 + tid] = hsum2(acc0);
        sg[1 * 512 + tid] = hsum2(acc1);
        sg[2 * 512 + tid] = hsum2(acc2);
        sg[3 * 512 + tid] = hsum2(acc3);
        __syncthreads();                                   // S4

        // --- Phase F: LSTM cell update (i, f, g, o), element (q, j) ---
        {
            float gi = sg[q * 512 + j];
            float gf = sg[q * 512 + 128 + j];
            float gg = sg[q * 512 + 256 + j];
            float go = sg[q * 512 + 384 + j];
            float cn = sigmoidf_(gf) * sc[q * DD + j] + sigmoidf_(gi) * tanhf(gg);
            sc[q * DD + j] = cn;
            sh[q * DD + j] = sigmoidf_(go) * tanhf(cn);
        }
    }

    __syncthreads();

    // --- custom_loss ---
    sg[q * DD + j] = lsum;
    __syncthreads();
    if (tid < 4) {
        float s = 0.0f;
        for (int k = 0; k < 128; k++) s += sg[tid * DD + k];
        out_loss[b0 + tid] = s * (1.0f / T_STEPS);
    }
    __syncthreads();

    // --- predictions = relu(h @ Wd + bd) @ Wo + bo ---
    float pa = bd[j];
    for (int k = 0; k < 128; k++) {
        pa = fmaf(sh[q * DD + k], Wd[k * DD + j], pa);
    }
    sg[q * DD + j] = fmaxf(pa, 0.0f) * Wo[j];
    __syncthreads();
    if (tid < 4) {
        float s = 0.0f;
        for (int k = 0; k < 128; k++) s += sg[tid * DD + k];
        out_pred[b0 + tid] = s + bo[0];
    }
}

// ---------------------------------------------------------------------------
extern "C" void kernel_launch(void* const* d_in, const int* in_sizes, int n_in,
                              void* d_out, int out_size)
{
    const float* values = (const float*)d_in[0];
    const float* masks  = (const float*)d_in[1];
    const float* deltas = (const float*)d_in[2];
    const float* Wth    = (const float*)d_in[3];
    const float* bth    = (const float*)d_in[4];
    const float* Wtx    = (const float*)d_in[5];
    const float* btx    = (const float*)d_in[6];
    const float* Whr    = (const float*)d_in[7];
    const float* bhr    = (const float*)d_in[8];
    const float* Wfr    = (const float*)d_in[9];
    const float* bfr    = (const float*)d_in[10];
    const float* Wwc    = (const float*)d_in[11];
    const float* bwc    = (const float*)d_in[12];
    const float* Wk     = (const float*)d_in[13];
    const float* Wr     = (const float*)d_in[14];
    const float* bl     = (const float*)d_in[15];
    const float* Wd     = (const float*)d_in[16];
    const float* bd     = (const float*)d_in[17];
    const float* Wo     = (const float*)d_in[18];
    const float* bo     = (const float*)d_in[19];

    float *pGh, *pGx, *pBeta, *pGm, *pDen, *pWthT, *pWtxT, *pWhrQ, *pWfrQ, *pWgQ;
    cudaGetSymbolAddress((void**)&pGh,   g_Gh);
    cudaGetSymbolAddress((void**)&pGx,   g_Gx);
    cudaGetSymbolAddress((void**)&pBeta, g_Beta);
    cudaGetSymbolAddress((void**)&pGm,   g_Gm);
    cudaGetSymbolAddress((void**)&pDen,  g_den);
    cudaGetSymbolAddress((void**)&pWthT, g_WthT);
    cudaGetSymbolAddress((void**)&pWtxT, g_WtxT);
    cudaGetSymbolAddress((void**)&pWhrQ, g_WhrQ);
    cudaGetSymbolAddress((void**)&pWfrQ, g_WfrQ);
    cudaGetSymbolAddress((void**)&pWgQ,  g_WgQ);

    // Launch 0: prep (incl. denom)
    prep_weights<<<512, 256>>>(Wth, Wtx, Whr, Wfr, Wk, Wr, masks,
                               pWthT, pWtxT, pWhrQ, pWfrQ, pWgQ, pDen);

    // Launch 1: merged GEMM (Gh, Gx, Gm)
    dim3 gm(1024, 12);
    gemm_merged<<<gm, 256>>>(deltas, masks, pWthT, bth, pWtxT, btx,
                             Wk + 128 * 512, bl, pGh, pGx, pGm);

    // Launch 2: Beta (consumes Gx)
    dim3 gb(1024, 2);
    gemm_beta<<<gb, 256>>>(pGx, masks, Wwc, bwc, pBeta);

    // Launch 3: sequential recurrence
    float* out = (float*)d_out;
    const size_t SMEM = (size_t)(16384 * 2 + N_STASH * 2048 + 512 * 4 + 2048 + 256)
                        * sizeof(float);   // 222,208 B
    cudaFuncSetAttribute(seq_kernel, cudaFuncAttributeMaxDynamicSharedMemorySize, (int)SMEM);
    seq_kernel<<<128, 512, SMEM>>>(values, masks, pWhrQ, bhr, bfr, pWfrQ,
                                   pGh, pBeta, pGm, pDen,
                                   Wd, bd, Wo, bo, pWgQ,
                                   out,                     // predictions [512]
                                   out + 512,               // imputations [512*128*128]
                                   out + 512 + 8388608);    // custom_loss [512]
}